// round 15
// baseline (speedup 1.0000x reference)
#include <cuda_runtime.h>
#include <cuda_bf16.h>

#define B_CONST 32
#define L_CONST 256
#define H_CONST 512
#define ROWS_PER_WARP   2
#define WARPS_PER_BLOCK 16
#define BLOCK_THREADS   (WARPS_PER_BLOCK * 32)              // 512
#define ROWS_PER_BLOCK  (ROWS_PER_WARP * WARPS_PER_BLOCK)   // 32

// Single fused kernel. 512-thread blocks: 16 warps x 2 rows/warp = 32 rows
// per block (halves the number of cumsum prologues vs R13 while keeping the
// EXACT per-warp work shape that measured best: one 9-step binary search +
// monotone walk, then MLP-8 front-batched LDG.128 and 8 streaming STG.128).
// Prologue: per-batch inclusive cumsum of durations via warp-shuffle scan
// (threads 0-255 only). Streaming stores (__stcs) keep x L2-resident. Rows
// past total are zeroed; mask written in-kernel.
__global__ void __launch_bounds__(BLOCK_THREADS) fused_kernel(
    const float4* __restrict__ x4,       // [B, L, 128]
    const int*    __restrict__ dur,      // [B, L]
    float4*       __restrict__ out4,     // [B, T, 128]
    float*        __restrict__ out_mask, // [B, T]
    int T)
{
    __shared__ int s_csum[L_CONST];
    __shared__ int s_wsum[8];

    int b    = blockIdx.y;
    int tid  = threadIdx.x;
    int lane = tid & 31;
    int w    = tid >> 5;

    // ---- per-batch scan of durations into s_csum (threads 0-255) ----
    if (tid < L_CONST) {
        int d = dur[b * L_CONST + tid];
        int v = d;
        #pragma unroll
        for (int off = 1; off < 32; off <<= 1) {
            int n = __shfl_up_sync(0xFFFFFFFFu, v, off);
            if (lane >= off) v += n;
        }
        if (lane == 31) s_wsum[w] = v;
        __syncthreads();
        if (w == 0) {
            int ws = (lane < 8) ? s_wsum[lane] : 0;
            #pragma unroll
            for (int off = 1; off < 8; off <<= 1) {
                int n = __shfl_up_sync(0xFFFFFFFFu, ws, off);
                if (lane >= off) ws += n;
            }
            if (lane < 8) s_wsum[lane] = ws;
        }
        __syncthreads();
        int base = (w > 0) ? s_wsum[w - 1] : 0;
        s_csum[tid] = base + v;
    } else {
        __syncthreads();
        __syncthreads();
    }
    __syncthreads();

    int total    = s_csum[L_CONST - 1];
    int t0_block = blockIdx.x * ROWS_PER_BLOCK;

    // ---- mask for this block's 32 rows ----
    if (tid < ROWS_PER_BLOCK) {
        int tm = t0_block + tid;
        if (tm < T)
            out_mask[(size_t)b * T + tm] = (tm < total) ? 1.0f : 0.0f;
    }

    // ---- expand: one warp per 2 consecutive rows ----
    int t0 = t0_block + w * ROWS_PER_WARP;
    if (t0 >= T) return;
    int t1 = t0 + 1;
    bool has_t1 = (t1 < T);

    // idx0 = searchsorted(csum, t0, 'right'): first l with csum[l] > t0.
    // [0,256) needs NINE bisection steps to fully resolve (lo==hi).
    int idx0 = -1;
    if (t0 < total) {
        int lo = 0, hi = L_CONST;
        #pragma unroll
        for (int step = 0; step < 9; ++step) {
            int mid = (lo + hi) >> 1;
            if (s_csum[mid] <= t0) lo = mid + 1; else hi = mid;
        }
        idx0 = lo;                       // <= L-1 since csum[L-1] = total > t0
    }
    // idx1: monotone advance from idx0
    int idx1 = -1;
    if (has_t1 && t1 < total) {
        int j = (idx0 >= 0) ? idx0 : 0;
        while (s_csum[j] <= t1) ++j;     // terminates: csum[L-1] > t1
        idx1 = j;
    }

    const float4 z = make_float4(0.f, 0.f, 0.f, 0.f);
    float4 v0 = z, v1 = z, v2 = z, v3 = z;
    float4 u0 = z, u1 = z, u2 = z, u3 = z;

    // front-batched loads: up to 8 independent LDG.128 in flight
    if (idx0 >= 0) {
        const float4* s = x4 + ((size_t)b * L_CONST + idx0) * 128 + lane;
        v0 = __ldg(s);
        v1 = __ldg(s + 32);
        v2 = __ldg(s + 64);
        v3 = __ldg(s + 96);
    }
    if (idx1 >= 0) {
        const float4* s = x4 + ((size_t)b * L_CONST + idx1) * 128 + lane;
        u0 = __ldg(s);
        u1 = __ldg(s + 32);
        u2 = __ldg(s + 64);
        u3 = __ldg(s + 96);
    }

    float4* d0 = out4 + ((size_t)b * T + t0) * 128 + lane;
    __stcs(d0,      v0);
    __stcs(d0 + 32, v1);
    __stcs(d0 + 64, v2);
    __stcs(d0 + 96, v3);

    if (has_t1) {
        float4* d1 = d0 + 128;
        __stcs(d1,      u0);
        __stcs(d1 + 32, u1);
        __stcs(d1 + 64, u2);
        __stcs(d1 + 96, u3);
    }
}

extern "C" void kernel_launch(void* const* d_in, const int* in_sizes, int n_in,
                              void* d_out, int out_size) {
    const float* x;
    const int*   dur;
    if (in_sizes[0] == B_CONST * L_CONST) {
        dur = (const int*)d_in[0];
        x   = (const float*)d_in[1];
    } else {
        x   = (const float*)d_in[0];
        dur = (const int*)d_in[1];
    }

    int T = out_size / (B_CONST * (H_CONST + 1));

    float* out      = (float*)d_out;
    float* out_mask = out + (size_t)B_CONST * T * H_CONST;

    dim3 grid((T + ROWS_PER_BLOCK - 1) / ROWS_PER_BLOCK, B_CONST);
    fused_kernel<<<grid, BLOCK_THREADS>>>(
        (const float4*)x, dur, (float4*)out, out_mask, T);
}

// round 16
// speedup vs baseline: 1.0366x; 1.0366x over previous
#include <cuda_runtime.h>
#include <cuda_bf16.h>

#define B_CONST 32
#define L_CONST 256
#define H_CONST 512
#define ROWS_PER_WARP   2
#define WARPS_PER_BLOCK 8
#define ROWS_PER_BLOCK  (ROWS_PER_WARP * WARPS_PER_BLOCK)   // 16

// Final converged kernel (R13 configuration — best measured: 24.67us total).
// Single fused kernel, ~4192 blocks of 256 threads. Each block serves one
// batch b and 16 consecutive output rows. Prologue: per-batch inclusive
// cumsum of durations (1KB, L2-hot) via warp-shuffle scan into shared. Each
// warp handles 2 consecutive rows: one 9-step binary search for row t0
// ([0,256) requires NINE bisection steps to fully resolve), monotone walk for
// t0+1, then BOTH source rows loaded front-batched (8 independent LDG.128 =
// MLP 8) followed by 8 streaming STG.128 (__stcs keeps x L2-resident). Rows
// past total are zeroed; mask written in-kernel. The kernel is pinned at the
// HBM write-stream floor (137MB mandatory output writes @ ~5.5TB/s).
__global__ void __launch_bounds__(256) fused_kernel(
    const float4* __restrict__ x4,       // [B, L, 128]
    const int*    __restrict__ dur,      // [B, L]
    float4*       __restrict__ out4,     // [B, T, 128]
    float*        __restrict__ out_mask, // [B, T]
    int T)
{
    __shared__ int s_csum[L_CONST];
    __shared__ int s_wsum[8];

    int b    = blockIdx.y;
    int tid  = threadIdx.x;
    int lane = tid & 31;
    int w    = tid >> 5;

    // ---- per-batch scan of durations into s_csum (inclusive) ----
    int d = dur[b * L_CONST + tid];
    int v = d;
    #pragma unroll
    for (int off = 1; off < 32; off <<= 1) {
        int n = __shfl_up_sync(0xFFFFFFFFu, v, off);
        if (lane >= off) v += n;
    }
    if (lane == 31) s_wsum[w] = v;
    __syncthreads();
    if (w == 0) {
        int ws = (lane < 8) ? s_wsum[lane] : 0;
        #pragma unroll
        for (int off = 1; off < 8; off <<= 1) {
            int n = __shfl_up_sync(0xFFFFFFFFu, ws, off);
            if (lane >= off) ws += n;
        }
        if (lane < 8) s_wsum[lane] = ws;
    }
    __syncthreads();
    int base = (w > 0) ? s_wsum[w - 1] : 0;
    s_csum[tid] = base + v;
    __syncthreads();

    int total    = s_csum[L_CONST - 1];
    int t0_block = blockIdx.x * ROWS_PER_BLOCK;

    // ---- mask for this block's 16 rows ----
    if (tid < ROWS_PER_BLOCK) {
        int tm = t0_block + tid;
        if (tm < T)
            out_mask[(size_t)b * T + tm] = (tm < total) ? 1.0f : 0.0f;
    }

    // ---- expand: one warp per 2 consecutive rows ----
    int t0 = t0_block + w * ROWS_PER_WARP;
    if (t0 >= T) return;
    int t1 = t0 + 1;
    bool has_t1 = (t1 < T);

    // idx0 = searchsorted(csum, t0, 'right'): first l with csum[l] > t0.
    int idx0 = -1;
    if (t0 < total) {
        int lo = 0, hi = L_CONST;
        #pragma unroll
        for (int step = 0; step < 9; ++step) {
            int mid = (lo + hi) >> 1;
            if (s_csum[mid] <= t0) lo = mid + 1; else hi = mid;
        }
        idx0 = lo;                       // <= L-1 since csum[L-1] = total > t0
    }
    // idx1: monotone advance from idx0
    int idx1 = -1;
    if (has_t1 && t1 < total) {
        int j = (idx0 >= 0) ? idx0 : 0;
        while (s_csum[j] <= t1) ++j;     // terminates: csum[L-1] > t1
        idx1 = j;
    }

    const float4 z = make_float4(0.f, 0.f, 0.f, 0.f);
    float4 v0 = z, v1 = z, v2 = z, v3 = z;
    float4 u0 = z, u1 = z, u2 = z, u3 = z;

    // front-batched loads: up to 8 independent LDG.128 in flight
    if (idx0 >= 0) {
        const float4* s = x4 + ((size_t)b * L_CONST + idx0) * 128 + lane;
        v0 = __ldg(s);
        v1 = __ldg(s + 32);
        v2 = __ldg(s + 64);
        v3 = __ldg(s + 96);
    }
    if (idx1 >= 0) {
        const float4* s = x4 + ((size_t)b * L_CONST + idx1) * 128 + lane;
        u0 = __ldg(s);
        u1 = __ldg(s + 32);
        u2 = __ldg(s + 64);
        u3 = __ldg(s + 96);
    }

    float4* d0 = out4 + ((size_t)b * T + t0) * 128 + lane;
    __stcs(d0,      v0);
    __stcs(d0 + 32, v1);
    __stcs(d0 + 64, v2);
    __stcs(d0 + 96, v3);

    if (has_t1) {
        float4* d1 = d0 + 128;
        __stcs(d1,      u0);
        __stcs(d1 + 32, u1);
        __stcs(d1 + 64, u2);
        __stcs(d1 + 96, u3);
    }
}

extern "C" void kernel_launch(void* const* d_in, const int* in_sizes, int n_in,
                              void* d_out, int out_size) {
    const float* x;
    const int*   dur;
    if (in_sizes[0] == B_CONST * L_CONST) {
        dur = (const int*)d_in[0];
        x   = (const float*)d_in[1];
    } else {
        x   = (const float*)d_in[0];
        dur = (const int*)d_in[1];
    }

    int T = out_size / (B_CONST * (H_CONST + 1));

    float* out      = (float*)d_out;
    float* out_mask = out + (size_t)B_CONST * T * H_CONST;

    dim3 grid((T + ROWS_PER_BLOCK - 1) / ROWS_PER_BLOCK, B_CONST);
    fused_kernel<<<grid, 256>>>(
        (const float4*)x, dur, (float4*)out, out_mask, T);
}